// round 1
// baseline (speedup 1.0000x reference)
#include <cuda_runtime.h>
#include <math.h>

#define BDIM 8
#define TDIM 8192
#define BT (BDIM*TDIM)
#define HDIM 512
#define SSDIM 32

// Scratch (device globals; no allocations allowed)
__device__ float g_hf[BT*64];              // pre-conv hash features
__device__ float g_h[BT*HDIM];             // activations ping
__device__ float g_h2[BT*HDIM];            // activations pong
__device__ float g_gates[BDIM*SSDIM*TDIM]; // (B,S,T)
__device__ float g_drive[BDIM*SSDIM*TDIM]; // (B,S,T)
__device__ float g_states[BDIM*SSDIM*TDIM];// (B,S,T)

__device__ __forceinline__ float silu_f(float x) { return x / (1.f + __expf(-x)); }

// ---------------------------------------------------------------------------
// K1: rolling hashes + scale attention -> pre-conv hash_feat (B,T,64)
// one warp per token
// ---------------------------------------------------------------------------
__global__ void __launch_bounds__(256) k_hashfeat(
    const int* __restrict__ chars, const float* __restrict__ emb_byte,
    const float* __restrict__ htab, const float* __restrict__ Wq,
    const float* __restrict__ bq)
{
    int gw = (blockIdx.x * blockDim.x + threadIdx.x) >> 5;
    if (gw >= BT) return;
    int lane = threadIdx.x & 31;
    int wip  = threadIdx.x >> 5;
    int b = gw / TDIM, t = gw % TDIM;
    const int* cb = chars + b * TDIM;

    int myc = (lane < 16 && t >= lane) ? cb[t - lane] : 0;

    int acc0 = 0, acc1 = 0, acc2 = 0, acc3 = 0;
    int p = 1;
#pragma unroll
    for (int j = 0; j < 16; j++) {
        int cj = __shfl_sync(0xffffffffu, myc, j);
        int term = cj * p;
        if (j < 2) acc0 += term;
        if (j < 4) acc1 += term;
        if (j < 8) acc2 += term;
        acc3 += term;
        p = (p * 257) & 4095;
    }
    int h0 = acc0 & 4095, h1 = acc1 & 4095, h2 = acc2 & 4095, h3 = acc3 & 4095;

    int c0 = lane * 2;
    int ch0 = __shfl_sync(0xffffffffu, myc, 0);
    float2 be = *(const float2*)&emb_byte[ch0 * 64 + c0];

    __shared__ float s_be[8][64];
    s_be[wip][c0]     = be.x;
    s_be[wip][c0 + 1] = be.y;
    __syncwarp();

    float q0 = bq[c0], q1 = bq[c0 + 1];
#pragma unroll 8
    for (int k = 0; k < 64; k++) {
        float bk = s_be[wip][k];
        q0 = fmaf(bk, Wq[k * 64 + c0],     q0);
        q1 = fmaf(bk, Wq[k * 64 + c0 + 1], q1);
    }

    float2 se0 = *(const float2*)&htab[(size_t)(0 * 4096 + h0) * 64 + c0];
    float2 se1 = *(const float2*)&htab[(size_t)(1 * 4096 + h1) * 64 + c0];
    float2 se2 = *(const float2*)&htab[(size_t)(2 * 4096 + h2) * 64 + c0];
    float2 se3 = *(const float2*)&htab[(size_t)(3 * 4096 + h3) * 64 + c0];

    float s0 = q0 * se0.x + q1 * se0.y;
    float s1 = q0 * se1.x + q1 * se1.y;
    float s2 = q0 * se2.x + q1 * se2.y;
    float s3 = q0 * se3.x + q1 * se3.y;
#pragma unroll
    for (int off = 16; off; off >>= 1) {
        s0 += __shfl_xor_sync(0xffffffffu, s0, off);
        s1 += __shfl_xor_sync(0xffffffffu, s1, off);
        s2 += __shfl_xor_sync(0xffffffffu, s2, off);
        s3 += __shfl_xor_sync(0xffffffffu, s3, off);
    }
    s0 *= 0.125f; s1 *= 0.125f; s2 *= 0.125f; s3 *= 0.125f;
    float m = fmaxf(fmaxf(s0, s1), fmaxf(s2, s3));
    float e0 = __expf(s0 - m), e1 = __expf(s1 - m), e2 = __expf(s2 - m), e3 = __expf(s3 - m);
    float inv = 1.f / (e0 + e1 + e2 + e3);
    float o0 = (e0 * se0.x + e1 * se1.x + e2 * se2.x + e3 * se3.x) * inv;
    float o1 = (e0 * se0.y + e1 * se1.y + e2 * se2.y + e3 * se3.y) * inv;
    *(float2*)&g_hf[(size_t)gw * 64 + c0] = make_float2(o0, o1);
}

// ---------------------------------------------------------------------------
// K2: depthwise conv + silu + byte emb + match feats, fused with feat@Win+silu
// block = 32 tokens, 256 threads; each thread 2 cols x 32 tokens
// ---------------------------------------------------------------------------
__global__ void __launch_bounds__(256) k_feat_win(
    const int* __restrict__ chars, const float* __restrict__ emb_byte,
    const float* __restrict__ conv_w, const float* __restrict__ conv_b,
    const float* __restrict__ Win, const float* __restrict__ b_in)
{
    __shared__ float sf[32][132];
    __shared__ int sch[32];
    int blk = blockIdx.x;
    int b = blk / (TDIM / 32);
    int tBase = (blk % (TDIM / 32)) * 32;
    int tid = threadIdx.x;
    const int* cb = chars + b * TDIM;

    if (tid < 32) sch[tid] = cb[tBase + tid];
    __syncthreads();

    // byte emb
    for (int idx = tid; idx < 32 * 64; idx += 256) {
        int tok = idx >> 6, c = idx & 63;
        sf[tok][c] = emb_byte[sch[tok] * 64 + c];
    }
    // causal depthwise conv + silu
    for (int idx = tid; idx < 32 * 64; idx += 256) {
        int tok = idx >> 6, c = idx & 63;
        int t = tBase + tok;
        float acc = conv_b[c];
#pragma unroll
        for (int k = 0; k < 4; k++) {
            int tt = t - 3 + k;
            float v = (tt >= 0) ? g_hf[(size_t)(b * TDIM + tt) * 64 + c] : 0.f;
            acc = fmaf(conv_w[c * 4 + k], v, acc);
        }
        sf[tok][64 + c] = silu_f(acc);
    }
    // match features
    for (int idx = tid; idx < 128; idx += 256) {
        int tok = idx >> 2, mm = idx & 3;
        int k = 1 << mm; // 1,2,4,8
        int t = tBase + tok;
        float v = 0.f;
        if (t >= k) v = (cb[t] == cb[t - k]) ? 1.f : 0.f;
        sf[tok][128 + mm] = v;
    }
    __syncthreads();

    float acc0[32], acc1[32];
#pragma unroll
    for (int i = 0; i < 32; i++) { acc0[i] = 0.f; acc1[i] = 0.f; }
    int col0 = tid, col1 = tid + 256;
    for (int k4 = 0; k4 < 132; k4 += 4) {
        float w00 = Win[(k4 + 0) * 512 + col0];
        float w10 = Win[(k4 + 1) * 512 + col0];
        float w20 = Win[(k4 + 2) * 512 + col0];
        float w30 = Win[(k4 + 3) * 512 + col0];
        float w01 = Win[(k4 + 0) * 512 + col1];
        float w11 = Win[(k4 + 1) * 512 + col1];
        float w21 = Win[(k4 + 2) * 512 + col1];
        float w31 = Win[(k4 + 3) * 512 + col1];
#pragma unroll
        for (int tok = 0; tok < 32; tok++) {
            float4 f = *(const float4*)&sf[tok][k4];
            acc0[tok] = fmaf(f.x, w00, acc0[tok]);
            acc0[tok] = fmaf(f.y, w10, acc0[tok]);
            acc0[tok] = fmaf(f.z, w20, acc0[tok]);
            acc0[tok] = fmaf(f.w, w30, acc0[tok]);
            acc1[tok] = fmaf(f.x, w01, acc1[tok]);
            acc1[tok] = fmaf(f.y, w11, acc1[tok]);
            acc1[tok] = fmaf(f.z, w21, acc1[tok]);
            acc1[tok] = fmaf(f.w, w31, acc1[tok]);
        }
    }
    float bv0 = b_in[col0], bv1 = b_in[col1];
#pragma unroll
    for (int tok = 0; tok < 32; tok++) {
        size_t base = (size_t)(b * TDIM + tBase + tok) * 512;
        g_h[base + col0] = silu_f(acc0[tok] + bv0);
        g_h[base + col1] = silu_f(acc1[tok] + bv1);
    }
}

// ---------------------------------------------------------------------------
// K3: gates/drive. block = 8 tokens (8 warps); writes (B,S,T) layout
// ---------------------------------------------------------------------------
__global__ void __launch_bounds__(256) k_gates(
    const float* __restrict__ Wg, const float* __restrict__ bg,
    const float* __restrict__ Wi, const float* __restrict__ bi)
{
    __shared__ float sh[8][512];
    int n0 = blockIdx.x * 8;
    int tid = threadIdx.x;
    for (int i = tid; i < 8 * 128; i += 256) {
        int tok = i >> 7;
        int k4 = (i & 127) * 4;
        *(float4*)&sh[tok][k4] = *(const float4*)&g_h[(size_t)(n0 + tok) * 512 + k4];
    }
    __syncthreads();
    int w = tid >> 5, lane = tid & 31;
    int n = n0 + w;
    float ag = bg[lane], ai = bi[lane];
#pragma unroll 8
    for (int k = 0; k < 512; k++) {
        float hv = sh[w][k];
        ag = fmaf(hv, Wg[k * 32 + lane], ag);
        ai = fmaf(hv, Wi[k * 32 + lane], ai);
    }
    float g = 1.f / (1.f + __expf(-ag));
    float d = (1.f - g) * ai;
    int b = n / TDIM, t = n % TDIM;
    g_gates[(size_t)(b * SSDIM + lane) * TDIM + t] = g;
    g_drive[(size_t)(b * SSDIM + lane) * TDIM + t] = d;
}

// ---------------------------------------------------------------------------
// K4: chunk-parallel TinyScan. one block per (b,s); thread = one 32-chunk.
// ---------------------------------------------------------------------------
__global__ void __launch_bounds__(256) k_scan()
{
    int bs = blockIdx.x;
    int j = threadIdx.x; // chunk index 0..255
    const float* ga = g_gates + (size_t)bs * TDIM + j * 32;
    const float* dr = g_drive + (size_t)bs * TDIM + j * 32;
    float a[32], bb[32];
#pragma unroll
    for (int i = 0; i < 32; i++) {
        a[i]  = fmaxf(ga[i], 1e-6f);
        bb[i] = dr[i];
    }
    float cumA = 1.f, cumWB = 0.f;
#pragma unroll
    for (int i = 0; i < 32; i++) {
        cumA *= a[i];
        float inv = 1.f / fmaxf(cumA, 1e-8f);
        cumWB = fmaf(bb[i], inv, cumWB);
    }
    __shared__ float sA[256], sB[256];
    sA[j] = cumA;
    sB[j] = cumA * cumWB;
    __syncthreads();
    // Hillis-Steele inclusive scan of linear maps (A2,B2)o(A1,B1)=(A2A1, A2B1+B2)
    for (int d = 1; d < 256; d <<= 1) {
        float a2 = sA[j], b2 = sB[j], a1 = 0.f, b1 = 0.f;
        if (j >= d) { a1 = sA[j - d]; b1 = sB[j - d]; }
        __syncthreads();
        if (j >= d) { sA[j] = a2 * a1; sB[j] = fmaf(a2, b1, b2); }
        __syncthreads();
    }
    float hc = (j == 0) ? 0.f : sB[j - 1];
    // replay
    cumA = 1.f; cumWB = 0.f;
    float* st = g_states + (size_t)bs * TDIM + j * 32;
#pragma unroll
    for (int i = 0; i < 32; i++) {
        cumA *= a[i];
        float inv = 1.f / fmaxf(cumA, 1e-8f);
        cumWB = fmaf(bb[i], inv, cumWB);
        st[i] = cumA * (hc + cumWB);
    }
}

// ---------------------------------------------------------------------------
// K5: h2 = LayerNorm(h + states@Wo + bo). block per token, 128 threads
// ---------------------------------------------------------------------------
__global__ void __launch_bounds__(128) k_wo_ln(
    const float* __restrict__ Wo, const float* __restrict__ bo,
    const float* __restrict__ lng, const float* __restrict__ lnb)
{
    int n = blockIdx.x;
    int b = n / TDIM, t = n % TDIM;
    int tid = threadIdx.x;
    __shared__ float sst[32];
    if (tid < 32) sst[tid] = g_states[(size_t)(b * SSDIM + tid) * TDIM + t];
    __syncthreads();

    int c = tid * 4;
    float4 hv = *(const float4*)&g_h[(size_t)n * 512 + c];
    float4 bv = *(const float4*)&bo[c];
    float y0 = hv.x + bv.x, y1 = hv.y + bv.y, y2 = hv.z + bv.z, y3 = hv.w + bv.w;
#pragma unroll
    for (int s = 0; s < 32; s++) {
        float sv = sst[s];
        float4 wv = *(const float4*)&Wo[s * 512 + c];
        y0 = fmaf(sv, wv.x, y0);
        y1 = fmaf(sv, wv.y, y1);
        y2 = fmaf(sv, wv.z, y2);
        y3 = fmaf(sv, wv.w, y3);
    }
    float lsum = y0 + y1 + y2 + y3;
    float lsq  = y0 * y0 + y1 * y1 + y2 * y2 + y3 * y3;
#pragma unroll
    for (int off = 16; off; off >>= 1) {
        lsum += __shfl_xor_sync(0xffffffffu, lsum, off);
        lsq  += __shfl_xor_sync(0xffffffffu, lsq,  off);
    }
    __shared__ float red[4][2];
    int wip = tid >> 5, lane = tid & 31;
    if (lane == 0) { red[wip][0] = lsum; red[wip][1] = lsq; }
    __syncthreads();
    lsum = red[0][0] + red[1][0] + red[2][0] + red[3][0];
    lsq  = red[0][1] + red[1][1] + red[2][1] + red[3][1];
    float mu = lsum * (1.f / 512.f);
    float var = lsq * (1.f / 512.f) - mu * mu;
    float rstd = rsqrtf(var + 1e-5f);
    float4 g4 = *(const float4*)&lng[c];
    float4 b4 = *(const float4*)&lnb[c];
    float4 o;
    o.x = (y0 - mu) * rstd * g4.x + b4.x;
    o.y = (y1 - mu) * rstd * g4.y + b4.y;
    o.z = (y2 - mu) * rstd * g4.z + b4.z;
    o.w = (y3 - mu) * rstd * g4.w + b4.w;
    *(float4*)&g_h2[(size_t)n * 512 + c] = o;
}

// ---------------------------------------------------------------------------
// Generic GEMM: Y = [RES? X + ] act(X@W + b). block = 32 tokens, 256 threads
// ---------------------------------------------------------------------------
template<int KDIM, int NC, int RES, int ACT>
__global__ void __launch_bounds__(256) k_gemm(
    const float* __restrict__ X, const float* __restrict__ W,
    const float* __restrict__ bias, float* __restrict__ Y)
{
    constexpr int KT = 128;
    constexpr int CPT = NC / 256;
    __shared__ float sx[32][KT];
    float acc[32][CPT];
#pragma unroll
    for (int i = 0; i < 32; i++)
#pragma unroll
        for (int cc = 0; cc < CPT; cc++) acc[i][cc] = 0.f;

    int tid = threadIdx.x;
    int n0 = blockIdx.x * 32;

    for (int kb = 0; kb < KDIM; kb += KT) {
        __syncthreads();
#pragma unroll
        for (int i = tid; i < 32 * (KT / 4); i += 256) {
            int tok = i >> 5;
            int k4 = (i & 31) * 4;
            *(float4*)&sx[tok][k4] =
                *(const float4*)&X[(size_t)(n0 + tok) * KDIM + kb + k4];
        }
        __syncthreads();
        for (int k4 = 0; k4 < KT; k4 += 4) {
            float w[4][CPT];
#pragma unroll
            for (int jj = 0; jj < 4; jj++)
#pragma unroll
                for (int cc = 0; cc < CPT; cc++)
                    w[jj][cc] = W[(size_t)(kb + k4 + jj) * NC + tid + cc * 256];
#pragma unroll
            for (int tok = 0; tok < 32; tok++) {
                float4 f = *(const float4*)&sx[tok][k4];
#pragma unroll
                for (int cc = 0; cc < CPT; cc++) {
                    acc[tok][cc] = fmaf(f.x, w[0][cc], acc[tok][cc]);
                    acc[tok][cc] = fmaf(f.y, w[1][cc], acc[tok][cc]);
                    acc[tok][cc] = fmaf(f.z, w[2][cc], acc[tok][cc]);
                    acc[tok][cc] = fmaf(f.w, w[3][cc], acc[tok][cc]);
                }
            }
        }
    }
#pragma unroll
    for (int cc = 0; cc < CPT; cc++) {
        int col = tid + cc * 256;
        float bv = bias[col];
#pragma unroll
        for (int tok = 0; tok < 32; tok++) {
            float v = acc[tok][cc] + bv;
            if (ACT) v = silu_f(v);
            if (RES) v += X[(size_t)(n0 + tok) * KDIM + col];
            Y[(size_t)(n0 + tok) * NC + col] = v;
        }
    }
}

// ---------------------------------------------------------------------------
extern "C" void kernel_launch(void* const* d_in, const int* in_sizes, int n_in,
                              void* d_out, int out_size)
{
    const int*   chars    = (const int*)d_in[0];
    const float* emb_byte = (const float*)d_in[1];
    const float* htab     = (const float*)d_in[2];
    const float* Wq       = (const float*)d_in[3];
    const float* bq       = (const float*)d_in[4];
    const float* conv_w   = (const float*)d_in[5];
    const float* conv_b   = (const float*)d_in[6];
    const float* Win      = (const float*)d_in[7];
    const float* b_in     = (const float*)d_in[8];
    const float* Wg       = (const float*)d_in[9];
    const float* bg       = (const float*)d_in[10];
    const float* Wi       = (const float*)d_in[11];
    const float* bi       = (const float*)d_in[12];
    const float* Wo       = (const float*)d_in[13];
    const float* bo       = (const float*)d_in[14];
    const float* lng      = (const float*)d_in[15];
    const float* lnb      = (const float*)d_in[16];
    const float* mlp_w    = (const float*)d_in[17];
    const float* mlp_b    = (const float*)d_in[18];
    const float* Wout     = (const float*)d_in[19];
    const float* bout     = (const float*)d_in[20];
    float* out = (float*)d_out;

    void *ph = 0, *ph2 = 0;
    cudaGetSymbolAddress(&ph,  g_h);
    cudaGetSymbolAddress(&ph2, g_h2);
    float* gh  = (float*)ph;
    float* gh2 = (float*)ph2;

    k_hashfeat<<<BT / 8, 256>>>(chars, emb_byte, htab, Wq, bq);
    k_feat_win<<<BT / 32, 256>>>(chars, emb_byte, conv_w, conv_b, Win, b_in);
    k_gates<<<BT / 8, 256>>>(Wg, bg, Wi, bi);
    k_scan<<<BDIM * SSDIM, 256>>>();
    k_wo_ln<<<BT, 128>>>(Wo, bo, lng, lnb);
    // residual MLPs: h2 -> h -> h2 -> h
    k_gemm<512, 512, 1, 1><<<BT / 32, 256>>>(gh2, mlp_w,                 mlp_b,        gh);
    k_gemm<512, 512, 1, 1><<<BT / 32, 256>>>(gh,  mlp_w + 512 * 512,     mlp_b + 512,  gh2);
    k_gemm<512, 512, 1, 1><<<BT / 32, 256>>>(gh2, mlp_w + 2 * 512 * 512, mlp_b + 1024, gh);
    // output head
    k_gemm<512, 256, 0, 0><<<BT / 32, 256>>>(gh, Wout, bout, out);
}

// round 2
// speedup vs baseline: 1.2202x; 1.2202x over previous
#include <cuda_runtime.h>
#include <math.h>

#define BDIM 8
#define TDIM 8192
#define BT (BDIM*TDIM)
#define HDIM 512
#define SSDIM 32

typedef unsigned long long u64;

// Scratch (device globals; no allocations allowed)
__device__ float g_hf[BT*64];              // pre-conv hash features
__device__ float g_h[BT*HDIM];             // activations ping
__device__ float g_h2[BT*HDIM];            // activations pong
__device__ float g_gates[BDIM*SSDIM*TDIM]; // (B,S,T)
__device__ float g_drive[BDIM*SSDIM*TDIM]; // (B,S,T)
__device__ float g_states[BDIM*SSDIM*TDIM];// (B,S,T)

__device__ __forceinline__ float silu_f(float x) { return x / (1.f + __expf(-x)); }

__device__ __forceinline__ u64 pack2(float x) {
    u64 r; asm("mov.b64 %0, {%1, %1};" : "=l"(r) : "f"(x)); return r;
}
__device__ __forceinline__ void ffma2(u64& d, u64 a, u64 b) {
    asm("fma.rn.f32x2 %0, %1, %2, %3;" : "=l"(d) : "l"(a), "l"(b), "l"(d));
}
__device__ __forceinline__ float lo32(u64 v) { return __uint_as_float((unsigned)v); }
__device__ __forceinline__ float hi32(u64 v) { return __uint_as_float((unsigned)(v >> 32)); }

// ---------------------------------------------------------------------------
// K1: rolling hashes + scale attention -> pre-conv hash_feat (B,T,64)
// one warp per token
// ---------------------------------------------------------------------------
__global__ void __launch_bounds__(256) k_hashfeat(
    const int* __restrict__ chars, const float* __restrict__ emb_byte,
    const float* __restrict__ htab, const float* __restrict__ Wq,
    const float* __restrict__ bq)
{
    int gw = (blockIdx.x * blockDim.x + threadIdx.x) >> 5;
    if (gw >= BT) return;
    int lane = threadIdx.x & 31;
    int wip  = threadIdx.x >> 5;
    int b = gw / TDIM, t = gw % TDIM;
    const int* cb = chars + b * TDIM;

    int myc = (lane < 16 && t >= lane) ? cb[t - lane] : 0;

    int acc0 = 0, acc1 = 0, acc2 = 0, acc3 = 0;
    int p = 1;
#pragma unroll
    for (int j = 0; j < 16; j++) {
        int cj = __shfl_sync(0xffffffffu, myc, j);
        int term = cj * p;
        if (j < 2) acc0 += term;
        if (j < 4) acc1 += term;
        if (j < 8) acc2 += term;
        acc3 += term;
        p = (p * 257) & 4095;
    }
    int h0 = acc0 & 4095, h1 = acc1 & 4095, h2 = acc2 & 4095, h3 = acc3 & 4095;

    int c0 = lane * 2;
    int ch0 = __shfl_sync(0xffffffffu, myc, 0);
    float2 be = *(const float2*)&emb_byte[ch0 * 64 + c0];

    __shared__ float s_be[8][64];
    s_be[wip][c0]     = be.x;
    s_be[wip][c0 + 1] = be.y;
    __syncwarp();

    float q0 = bq[c0], q1 = bq[c0 + 1];
#pragma unroll 8
    for (int k = 0; k < 64; k++) {
        float bk = s_be[wip][k];
        float2 wv = *(const float2*)&Wq[k * 64 + c0];
        q0 = fmaf(bk, wv.x, q0);
        q1 = fmaf(bk, wv.y, q1);
    }

    float2 se0 = *(const float2*)&htab[(size_t)(0 * 4096 + h0) * 64 + c0];
    float2 se1 = *(const float2*)&htab[(size_t)(1 * 4096 + h1) * 64 + c0];
    float2 se2 = *(const float2*)&htab[(size_t)(2 * 4096 + h2) * 64 + c0];
    float2 se3 = *(const float2*)&htab[(size_t)(3 * 4096 + h3) * 64 + c0];

    float s0 = q0 * se0.x + q1 * se0.y;
    float s1 = q0 * se1.x + q1 * se1.y;
    float s2 = q0 * se2.x + q1 * se2.y;
    float s3 = q0 * se3.x + q1 * se3.y;
#pragma unroll
    for (int off = 16; off; off >>= 1) {
        s0 += __shfl_xor_sync(0xffffffffu, s0, off);
        s1 += __shfl_xor_sync(0xffffffffu, s1, off);
        s2 += __shfl_xor_sync(0xffffffffu, s2, off);
        s3 += __shfl_xor_sync(0xffffffffu, s3, off);
    }
    s0 *= 0.125f; s1 *= 0.125f; s2 *= 0.125f; s3 *= 0.125f;
    float m = fmaxf(fmaxf(s0, s1), fmaxf(s2, s3));
    float e0 = __expf(s0 - m), e1 = __expf(s1 - m), e2 = __expf(s2 - m), e3 = __expf(s3 - m);
    float inv = 1.f / (e0 + e1 + e2 + e3);
    float o0 = (e0 * se0.x + e1 * se1.x + e2 * se2.x + e3 * se3.x) * inv;
    float o1 = (e0 * se0.y + e1 * se1.y + e2 * se2.y + e3 * se3.y) * inv;
    *(float2*)&g_hf[(size_t)gw * 64 + c0] = make_float2(o0, o1);
}

// ---------------------------------------------------------------------------
// K2: features (byte emb + conv-silu + match) staged TRANSPOSED, then
// paired-token FFMA2 GEMM feat(132) x Win(132,512) -> silu -> g_h
// block = 32 tokens, 256 threads, each thread 2 cols
// ---------------------------------------------------------------------------
__global__ void __launch_bounds__(256) k_feat_win(
    const int* __restrict__ chars, const float* __restrict__ emb_byte,
    const float* __restrict__ conv_w, const float* __restrict__ conv_b,
    const float* __restrict__ Win, const float* __restrict__ b_in)
{
    __shared__ float sxt[132][32];   // [k][tok]
    __shared__ int sch[32];
    int blk = blockIdx.x;
    int b = blk / (TDIM / 32);
    int tBase = (blk % (TDIM / 32)) * 32;
    int tid = threadIdx.x;
    const int* cb = chars + b * TDIM;

    if (tid < 32) sch[tid] = cb[tBase + tid];
    __syncthreads();

    for (int idx = tid; idx < 32 * 64; idx += 256) {
        int tok = idx >> 6, c = idx & 63;
        sxt[c][tok] = emb_byte[sch[tok] * 64 + c];
    }
    for (int idx = tid; idx < 32 * 64; idx += 256) {
        int tok = idx >> 6, c = idx & 63;
        int t = tBase + tok;
        float acc = conv_b[c];
#pragma unroll
        for (int k = 0; k < 4; k++) {
            int tt = t - 3 + k;
            float v = (tt >= 0) ? g_hf[(size_t)(b * TDIM + tt) * 64 + c] : 0.f;
            acc = fmaf(conv_w[c * 4 + k], v, acc);
        }
        sxt[64 + c][tok] = silu_f(acc);
    }
    for (int idx = tid; idx < 128; idx += 256) {
        int tok = idx >> 2, mm = idx & 3;
        int k = 1 << mm;
        int t = tBase + tok;
        float v = 0.f;
        if (t >= k) v = (cb[t] == cb[t - k]) ? 1.f : 0.f;
        sxt[128 + mm][tok] = v;
    }
    __syncthreads();

    u64 acc[16][2];
#pragma unroll
    for (int i = 0; i < 16; i++) { acc[i][0] = 0ull; acc[i][1] = 0ull; }

#pragma unroll 1
    for (int k4 = 0; k4 < 132; k4 += 4) {
        u64 wp[4][2];
#pragma unroll
        for (int j = 0; j < 4; j++) {
            wp[j][0] = pack2(Win[(size_t)(k4 + j) * 512 + tid]);
            wp[j][1] = pack2(Win[(size_t)(k4 + j) * 512 + tid + 256]);
        }
#pragma unroll
        for (int j = 0; j < 4; j++) {
            const ulonglong2* xr = (const ulonglong2*)&sxt[k4 + j][0];
#pragma unroll
            for (int q = 0; q < 8; q++) {
                ulonglong2 x2 = xr[q];
                ffma2(acc[2 * q][0],     x2.x, wp[j][0]);
                ffma2(acc[2 * q][1],     x2.x, wp[j][1]);
                ffma2(acc[2 * q + 1][0], x2.y, wp[j][0]);
                ffma2(acc[2 * q + 1][1], x2.y, wp[j][1]);
            }
        }
    }
#pragma unroll
    for (int cc = 0; cc < 2; cc++) {
        int col = tid + cc * 256;
        float bv = b_in[col];
#pragma unroll
        for (int p = 0; p < 16; p++) {
            size_t r0 = (size_t)(b * TDIM + tBase + 2 * p) * 512 + col;
            g_h[r0]       = silu_f(lo32(acc[p][cc]) + bv);
            g_h[r0 + 512] = silu_f(hi32(acc[p][cc]) + bv);
        }
    }
}

// ---------------------------------------------------------------------------
// K3: gates/drive GEMM-style. block = 32 tokens, 256 threads.
// col = tid&63 (cols 0..31 -> Wg, 32..63 -> Wi), kslice = tid>>6 (4 slices).
// ---------------------------------------------------------------------------
__global__ void __launch_bounds__(256) k_gates(
    const float* __restrict__ Wg, const float* __restrict__ bg,
    const float* __restrict__ Wi, const float* __restrict__ bi)
{
    __shared__ u64 smbuf[4096];                       // 32KB, dual-use
    float (*sxt)[32] = reinterpret_cast<float(*)[32]>(smbuf); // [128][32]

    int tid = threadIdx.x;
    int col = tid & 63;
    int ks  = tid >> 6;
    int n0 = blockIdx.x * 32;
    int b = n0 / TDIM, t0 = n0 % TDIM;

    u64 acc[16];
#pragma unroll
    for (int i = 0; i < 16; i++) acc[i] = 0ull;

    const float* Wsel = (col < 32) ? Wg : Wi;
    int wcol = col & 31;

    for (int kb = 0; kb < 512; kb += 128) {
        __syncthreads();
        for (int i = tid; i < 32 * 32; i += 256) {
            int tok = i & 31;
            int k4 = (i >> 5) << 2;
            float4 v = *(const float4*)&g_h[(size_t)(n0 + tok) * 512 + kb + k4];
            sxt[k4][tok] = v.x; sxt[k4 + 1][tok] = v.y;
            sxt[k4 + 2][tok] = v.z; sxt[k4 + 3][tok] = v.w;
        }
        __syncthreads();
        int kBase = ks * 32;
#pragma unroll 1
        for (int k = 0; k < 32; k++) {
            u64 wv = pack2(Wsel[(size_t)(kb + kBase + k) * 32 + wcol]);
            const ulonglong2* xr = (const ulonglong2*)&sxt[kBase + k][0];
#pragma unroll
            for (int q = 0; q < 8; q++) {
                ulonglong2 x2 = xr[q];
                ffma2(acc[2 * q],     x2.x, wv);
                ffma2(acc[2 * q + 1], x2.y, wv);
            }
        }
    }
    __syncthreads();
    // reduce 4 k-slices via smem: red[ks][col][p]
#pragma unroll
    for (int p = 0; p < 16; p++) smbuf[((size_t)ks * 64 + col) * 16 + p] = acc[p];
    __syncthreads();
    if (ks == 0 && col < 32) {
        int j = col;
        float bgv = bg[j], biv = bi[j];
        float* gout = g_gates + (size_t)(b * SSDIM + j) * TDIM + t0;
        float* dout = g_drive + (size_t)(b * SSDIM + j) * TDIM + t0;
#pragma unroll
        for (int p = 0; p < 16; p++) {
            float ag0 = bgv, ag1 = bgv, ai0 = biv, ai1 = biv;
#pragma unroll
            for (int s = 0; s < 4; s++) {
                u64 vg = smbuf[((size_t)s * 64 + j) * 16 + p];
                u64 vi = smbuf[((size_t)s * 64 + 32 + j) * 16 + p];
                ag0 += lo32(vg); ag1 += hi32(vg);
                ai0 += lo32(vi); ai1 += hi32(vi);
            }
            float g0 = 1.f / (1.f + __expf(-ag0));
            float g1 = 1.f / (1.f + __expf(-ag1));
            gout[2 * p]     = g0;
            gout[2 * p + 1] = g1;
            dout[2 * p]     = (1.f - g0) * ai0;
            dout[2 * p + 1] = (1.f - g1) * ai1;
        }
    }
}

// ---------------------------------------------------------------------------
// K4: chunk-parallel TinyScan. one block per (b,s); thread = one 32-chunk.
// ---------------------------------------------------------------------------
__global__ void __launch_bounds__(256) k_scan()
{
    int bs = blockIdx.x;
    int j = threadIdx.x;
    const float* ga = g_gates + (size_t)bs * TDIM + j * 32;
    const float* dr = g_drive + (size_t)bs * TDIM + j * 32;
    float a[32], bb[32];
#pragma unroll
    for (int i = 0; i < 32; i++) {
        a[i]  = fmaxf(ga[i], 1e-6f);
        bb[i] = dr[i];
    }
    float cumA = 1.f, cumWB = 0.f;
#pragma unroll
    for (int i = 0; i < 32; i++) {
        cumA *= a[i];
        float inv = 1.f / fmaxf(cumA, 1e-8f);
        cumWB = fmaf(bb[i], inv, cumWB);
    }
    __shared__ float sA[256], sB[256];
    sA[j] = cumA;
    sB[j] = cumA * cumWB;
    __syncthreads();
    for (int d = 1; d < 256; d <<= 1) {
        float a2 = sA[j], b2 = sB[j], a1 = 0.f, b1 = 0.f;
        if (j >= d) { a1 = sA[j - d]; b1 = sB[j - d]; }
        __syncthreads();
        if (j >= d) { sA[j] = a2 * a1; sB[j] = fmaf(a2, b1, b2); }
        __syncthreads();
    }
    float hc = (j == 0) ? 0.f : sB[j - 1];
    cumA = 1.f; cumWB = 0.f;
    float* st = g_states + (size_t)bs * TDIM + j * 32;
#pragma unroll
    for (int i = 0; i < 32; i++) {
        cumA *= a[i];
        float inv = 1.f / fmaxf(cumA, 1e-8f);
        cumWB = fmaf(bb[i], inv, cumWB);
        st[i] = cumA * (hc + cumWB);
    }
}

// ---------------------------------------------------------------------------
// K5a: y = h + states@Wo + bo  (pre-LN), 32-token tiles, FFMA2 paired tokens
// ---------------------------------------------------------------------------
__global__ void __launch_bounds__(256) k_wo(
    const float* __restrict__ Wo, const float* __restrict__ bo)
{
    __shared__ float sxt[32][32];   // [s][tok]
    int tid = threadIdx.x;
    int n0 = blockIdx.x * 32;
    int b = n0 / TDIM, t0 = n0 % TDIM;

    for (int i = tid; i < 32 * 8; i += 256) {
        int s = i >> 3, t4 = (i & 7) * 4;
        float4 v = *(const float4*)&g_states[(size_t)(b * SSDIM + s) * TDIM + t0 + t4];
        *(float4*)&sxt[s][t4] = v;
    }
    __syncthreads();

    u64 acc[16][2];
#pragma unroll
    for (int i = 0; i < 16; i++) { acc[i][0] = 0ull; acc[i][1] = 0ull; }

#pragma unroll 1
    for (int k4 = 0; k4 < 32; k4 += 4) {
        u64 wp[4][2];
#pragma unroll
        for (int j = 0; j < 4; j++) {
            wp[j][0] = pack2(Wo[(size_t)(k4 + j) * 512 + tid]);
            wp[j][1] = pack2(Wo[(size_t)(k4 + j) * 512 + tid + 256]);
        }
#pragma unroll
        for (int j = 0; j < 4; j++) {
            const ulonglong2* xr = (const ulonglong2*)&sxt[k4 + j][0];
#pragma unroll
            for (int q = 0; q < 8; q++) {
                ulonglong2 x2 = xr[q];
                ffma2(acc[2 * q][0],     x2.x, wp[j][0]);
                ffma2(acc[2 * q][1],     x2.x, wp[j][1]);
                ffma2(acc[2 * q + 1][0], x2.y, wp[j][0]);
                ffma2(acc[2 * q + 1][1], x2.y, wp[j][1]);
            }
        }
    }
#pragma unroll
    for (int cc = 0; cc < 2; cc++) {
        int col = tid + cc * 256;
        float bv = bo[col];
#pragma unroll
        for (int p = 0; p < 16; p++) {
            size_t r0 = (size_t)(n0 + 2 * p) * 512 + col;
            g_h2[r0]       = lo32(acc[p][cc]) + bv + g_h[r0];
            g_h2[r0 + 512] = hi32(acc[p][cc]) + bv + g_h[r0 + 512];
        }
    }
}

// ---------------------------------------------------------------------------
// K5b: in-place LayerNorm over g_h2 rows. block per token, 128 threads.
// ---------------------------------------------------------------------------
__global__ void __launch_bounds__(128) k_ln(
    const float* __restrict__ lng, const float* __restrict__ lnb)
{
    int n = blockIdx.x;
    int tid = threadIdx.x;
    int c = tid * 4;
    float4 y = *(const float4*)&g_h2[(size_t)n * 512 + c];
    float lsum = y.x + y.y + y.z + y.w;
    float lsq  = y.x * y.x + y.y * y.y + y.z * y.z + y.w * y.w;
#pragma unroll
    for (int off = 16; off; off >>= 1) {
        lsum += __shfl_xor_sync(0xffffffffu, lsum, off);
        lsq  += __shfl_xor_sync(0xffffffffu, lsq,  off);
    }
    __shared__ float red[4][2];
    int wip = tid >> 5, lane = tid & 31;
    if (lane == 0) { red[wip][0] = lsum; red[wip][1] = lsq; }
    __syncthreads();
    lsum = red[0][0] + red[1][0] + red[2][0] + red[3][0];
    lsq  = red[0][1] + red[1][1] + red[2][1] + red[3][1];
    float mu = lsum * (1.f / 512.f);
    float var = lsq * (1.f / 512.f) - mu * mu;
    float rstd = rsqrtf(var + 1e-5f);
    float4 g4 = *(const float4*)&lng[c];
    float4 b4 = *(const float4*)&lnb[c];
    float4 o;
    o.x = (y.x - mu) * rstd * g4.x + b4.x;
    o.y = (y.y - mu) * rstd * g4.y + b4.y;
    o.z = (y.z - mu) * rstd * g4.z + b4.z;
    o.w = (y.w - mu) * rstd * g4.w + b4.w;
    *(float4*)&g_h2[(size_t)n * 512 + c] = o;
}

// ---------------------------------------------------------------------------
// Paired-token FFMA2 GEMM: Y = [RES? X + ] act(X@W + b)
// block = 32 tokens, 256 threads; thread owns CPT cols, tokens packed in pairs
// ---------------------------------------------------------------------------
template<int KDIM, int NC, int RES, int ACT>
__global__ void __launch_bounds__(256) k_gemm(
    const float* __restrict__ X, const float* __restrict__ W,
    const float* __restrict__ bias, float* __restrict__ Y)
{
    constexpr int KT = 128;
    constexpr int CPT = NC / 256;
    __shared__ float sxt[KT][32];   // [k][tok]
    u64 acc[16][CPT];
#pragma unroll
    for (int i = 0; i < 16; i++)
#pragma unroll
        for (int cc = 0; cc < CPT; cc++) acc[i][cc] = 0ull;

    int tid = threadIdx.x;
    int n0 = blockIdx.x * 32;

    for (int kb = 0; kb < KDIM; kb += KT) {
        __syncthreads();
        for (int i = tid; i < 32 * (KT / 4); i += 256) {
            int tok = i & 31;
            int k4 = (i >> 5) << 2;
            float4 v = *(const float4*)&X[(size_t)(n0 + tok) * KDIM + kb + k4];
            sxt[k4][tok] = v.x; sxt[k4 + 1][tok] = v.y;
            sxt[k4 + 2][tok] = v.z; sxt[k4 + 3][tok] = v.w;
        }
        __syncthreads();
#pragma unroll 2
        for (int k4 = 0; k4 < KT; k4 += 4) {
            u64 wp[4][CPT];
#pragma unroll
            for (int j = 0; j < 4; j++)
#pragma unroll
                for (int cc = 0; cc < CPT; cc++)
                    wp[j][cc] = pack2(W[(size_t)(kb + k4 + j) * NC + tid + cc * 256]);
#pragma unroll
            for (int j = 0; j < 4; j++) {
                const ulonglong2* xr = (const ulonglong2*)&sxt[k4 + j][0];
#pragma unroll
                for (int q = 0; q < 8; q++) {
                    ulonglong2 x2 = xr[q];
#pragma unroll
                    for (int cc = 0; cc < CPT; cc++) {
                        ffma2(acc[2 * q][cc],     x2.x, wp[j][cc]);
                        ffma2(acc[2 * q + 1][cc], x2.y, wp[j][cc]);
                    }
                }
            }
        }
    }
#pragma unroll
    for (int cc = 0; cc < CPT; cc++) {
        int col = tid + cc * 256;
        float bv = bias[col];
#pragma unroll
        for (int p = 0; p < 16; p++) {
            float v0 = lo32(acc[p][cc]) + bv;
            float v1 = hi32(acc[p][cc]) + bv;
            if (ACT) { v0 = silu_f(v0); v1 = silu_f(v1); }
            if (RES) {
                v0 += X[(size_t)(n0 + 2 * p) * KDIM + col];
                v1 += X[(size_t)(n0 + 2 * p + 1) * KDIM + col];
            }
            Y[(size_t)(n0 + 2 * p) * NC + col]     = v0;
            Y[(size_t)(n0 + 2 * p + 1) * NC + col] = v1;
        }
    }
}

// ---------------------------------------------------------------------------
extern "C" void kernel_launch(void* const* d_in, const int* in_sizes, int n_in,
                              void* d_out, int out_size)
{
    const int*   chars    = (const int*)d_in[0];
    const float* emb_byte = (const float*)d_in[1];
    const float* htab     = (const float*)d_in[2];
    const float* Wq       = (const float*)d_in[3];
    const float* bq       = (const float*)d_in[4];
    const float* conv_w   = (const float*)d_in[5];
    const float* conv_b   = (const float*)d_in[6];
    const float* Win      = (const float*)d_in[7];
    const float* b_in     = (const float*)d_in[8];
    const float* Wg       = (const float*)d_in[9];
    const float* bg       = (const float*)d_in[10];
    const float* Wi       = (const float*)d_in[11];
    const float* bi       = (const float*)d_in[12];
    const float* Wo       = (const float*)d_in[13];
    const float* bo       = (const float*)d_in[14];
    const float* lng      = (const float*)d_in[15];
    const float* lnb      = (const float*)d_in[16];
    const float* mlp_w    = (const float*)d_in[17];
    const float* mlp_b    = (const float*)d_in[18];
    const float* Wout     = (const float*)d_in[19];
    const float* bout     = (const float*)d_in[20];
    float* out = (float*)d_out;

    void *ph = 0, *ph2 = 0;
    cudaGetSymbolAddress(&ph,  g_h);
    cudaGetSymbolAddress(&ph2, g_h2);
    float* gh  = (float*)ph;
    float* gh2 = (float*)ph2;

    k_hashfeat<<<BT / 8, 256>>>(chars, emb_byte, htab, Wq, bq);
    k_feat_win<<<BT / 32, 256>>>(chars, emb_byte, conv_w, conv_b, Win, b_in);
    k_gates<<<BT / 32, 256>>>(Wg, bg, Wi, bi);
    k_scan<<<BDIM * SSDIM, 256>>>();
    k_wo<<<BT / 32, 256>>>(Wo, bo);
    k_ln<<<BT, 128>>>(lng, lnb);
    // residual MLPs: h2 -> h -> h2 -> h
    k_gemm<512, 512, 1, 1><<<BT / 32, 256>>>(gh2, mlp_w,                 mlp_b,        gh);
    k_gemm<512, 512, 1, 1><<<BT / 32, 256>>>(gh,  mlp_w + 512 * 512,     mlp_b + 512,  gh2);
    k_gemm<512, 512, 1, 1><<<BT / 32, 256>>>(gh2, mlp_w + 2 * 512 * 512, mlp_b + 1024, gh);
    // output head
    k_gemm<512, 256, 0, 0><<<BT / 32, 256>>>(gh, Wout, bout, out);
}

// round 5
// speedup vs baseline: 2.0597x; 1.6880x over previous
#include <cuda_runtime.h>
#include <cuda_bf16.h>
#include <math.h>
#include <stdint.h>

#define BDIM 8
#define TDIM 8192
#define BT (BDIM*TDIM)
#define HDIM 512
#define SSDIM 32

typedef unsigned long long u64;

// ---------------- scratch (device globals; no allocations allowed) ----------
__device__ float g_hf[BT*64];
__device__ float g_h[BT*HDIM];
__device__ float g_h2[BT*HDIM];
__device__ float g_gates[BDIM*SSDIM*TDIM];
__device__ float g_drive[BDIM*SSDIM*TDIM];
__device__ float g_states[BDIM*SSDIM*TDIM];
// bf16 split activations (ping/pong pairs)
__device__ __nv_bfloat16 g_xh[(size_t)BT*512];
__device__ __nv_bfloat16 g_xl[(size_t)BT*512];
__device__ __nv_bfloat16 g_x2h[(size_t)BT*512];
__device__ __nv_bfloat16 g_x2l[(size_t)BT*512];
// bf16 split transposed weights [layer][n*512+k]
__device__ __nv_bfloat16 g_wbh[4][512*512];
__device__ __nv_bfloat16 g_wbl[4][512*512];

__device__ __forceinline__ float silu_f(float x) { return x / (1.f + __expf(-x)); }

__device__ __forceinline__ u64 pack2(float x) {
    u64 r; asm("mov.b64 %0, {%1, %1};" : "=l"(r) : "f"(x)); return r;
}
__device__ __forceinline__ void ffma2(u64& d, u64 a, u64 b) {
    asm("fma.rn.f32x2 %0, %1, %2, %3;" : "=l"(d) : "l"(a), "l"(b), "l"(d));
}
__device__ __forceinline__ float lo32(u64 v) { return __uint_as_float((unsigned)v); }
__device__ __forceinline__ float hi32(u64 v) { return __uint_as_float((unsigned)(v >> 32)); }

// ---------------- mma.sync / async helpers (arch-agnostic, sm_80+) ----------
__device__ __forceinline__ uint32_t smem_u32(const void* p) {
    uint32_t a;
    asm("{ .reg .u64 t; cvta.to.shared.u64 t, %1; cvt.u32.u64 %0, t; }" : "=r"(a) : "l"(p));
    return a;
}
#define CP_COMMIT()      asm volatile("cp.async.commit_group;" ::: "memory")
#define CP_WAIT1()       asm volatile("cp.async.wait_group 1;" ::: "memory")
#define CP_WAIT0()       asm volatile("cp.async.wait_group 0;" ::: "memory")

__device__ __forceinline__ void cpasync16(uint32_t dst, const void* src) {
    asm volatile("cp.async.cg.shared.global [%0], [%1], 16;" :: "r"(dst), "l"(src));
}
__device__ __forceinline__ void ldmx4(uint32_t* r, uint32_t addr) {
    asm volatile("ldmatrix.sync.aligned.m8n8.x4.shared.b16 {%0,%1,%2,%3}, [%4];"
        : "=r"(r[0]), "=r"(r[1]), "=r"(r[2]), "=r"(r[3]) : "r"(addr));
}
__device__ __forceinline__ void mma16816(float* c, const uint32_t* a,
                                         uint32_t b0, uint32_t b1) {
    asm volatile("mma.sync.aligned.m16n8k16.row.col.f32.bf16.bf16.f32 "
        "{%0,%1,%2,%3}, {%4,%5,%6,%7}, {%8,%9}, {%0,%1,%2,%3};"
        : "+f"(c[0]), "+f"(c[1]), "+f"(c[2]), "+f"(c[3])
        : "r"(a[0]), "r"(a[1]), "r"(a[2]), "r"(a[3]), "r"(b0), "r"(b1));
}
// 16B-granular XOR swizzle within a 128B row (conflict-free ldmatrix)
__device__ __forceinline__ uint32_t tile_addr(uint32_t tbase, int row, int c16) {
    return tbase + row * 128 + ((c16 ^ (row & 7)) << 4);
}

// ---------------------------------------------------------------------------
// K1: rolling hashes + scale attention -> g_hf (verified)
// ---------------------------------------------------------------------------
__global__ void __launch_bounds__(256) k_hashfeat(
    const int* __restrict__ chars, const float* __restrict__ emb_byte,
    const float* __restrict__ htab, const float* __restrict__ Wq,
    const float* __restrict__ bq)
{
    int gw = (blockIdx.x * blockDim.x + threadIdx.x) >> 5;
    if (gw >= BT) return;
    int lane = threadIdx.x & 31;
    int wip  = threadIdx.x >> 5;
    int b = gw / TDIM, t = gw % TDIM;
    const int* cb = chars + b * TDIM;

    int myc = (lane < 16 && t >= lane) ? cb[t - lane] : 0;

    int acc0 = 0, acc1 = 0, acc2 = 0, acc3 = 0;
    int p = 1;
#pragma unroll
    for (int j = 0; j < 16; j++) {
        int cj = __shfl_sync(0xffffffffu, myc, j);
        int term = cj * p;
        if (j < 2) acc0 += term;
        if (j < 4) acc1 += term;
        if (j < 8) acc2 += term;
        acc3 += term;
        p = (p * 257) & 4095;
    }
    int h0 = acc0 & 4095, h1 = acc1 & 4095, h2 = acc2 & 4095, h3 = acc3 & 4095;

    int c0 = lane * 2;
    int ch0 = __shfl_sync(0xffffffffu, myc, 0);
    float2 be = *(const float2*)&emb_byte[ch0 * 64 + c0];

    __shared__ float s_be[8][64];
    s_be[wip][c0]     = be.x;
    s_be[wip][c0 + 1] = be.y;
    __syncwarp();

    float q0 = bq[c0], q1 = bq[c0 + 1];
#pragma unroll 8
    for (int k = 0; k < 64; k++) {
        float bk = s_be[wip][k];
        float2 wv = *(const float2*)&Wq[k * 64 + c0];
        q0 = fmaf(bk, wv.x, q0);
        q1 = fmaf(bk, wv.y, q1);
    }

    float2 se0 = *(const float2*)&htab[(size_t)(0 * 4096 + h0) * 64 + c0];
    float2 se1 = *(const float2*)&htab[(size_t)(1 * 4096 + h1) * 64 + c0];
    float2 se2 = *(const float2*)&htab[(size_t)(2 * 4096 + h2) * 64 + c0];
    float2 se3 = *(const float2*)&htab[(size_t)(3 * 4096 + h3) * 64 + c0];

    float s0 = q0 * se0.x + q1 * se0.y;
    float s1 = q0 * se1.x + q1 * se1.y;
    float s2 = q0 * se2.x + q1 * se2.y;
    float s3 = q0 * se3.x + q1 * se3.y;
#pragma unroll
    for (int off = 16; off; off >>= 1) {
        s0 += __shfl_xor_sync(0xffffffffu, s0, off);
        s1 += __shfl_xor_sync(0xffffffffu, s1, off);
        s2 += __shfl_xor_sync(0xffffffffu, s2, off);
        s3 += __shfl_xor_sync(0xffffffffu, s3, off);
    }
    s0 *= 0.125f; s1 *= 0.125f; s2 *= 0.125f; s3 *= 0.125f;
    float m = fmaxf(fmaxf(s0, s1), fmaxf(s2, s3));
    float e0 = __expf(s0 - m), e1 = __expf(s1 - m), e2 = __expf(s2 - m), e3 = __expf(s3 - m);
    float inv = 1.f / (e0 + e1 + e2 + e3);
    float o0 = (e0 * se0.x + e1 * se1.x + e2 * se2.x + e3 * se3.x) * inv;
    float o1 = (e0 * se0.y + e1 * se1.y + e2 * se2.y + e3 * se3.y) * inv;
    *(float2*)&g_hf[(size_t)gw * 64 + c0] = make_float2(o0, o1);
}

// ---------------------------------------------------------------------------
// K2: features + Win GEMM (verified)
// ---------------------------------------------------------------------------
__global__ void __launch_bounds__(256) k_feat_win(
    const int* __restrict__ chars, const float* __restrict__ emb_byte,
    const float* __restrict__ conv_w, const float* __restrict__ conv_b,
    const float* __restrict__ Win, const float* __restrict__ b_in)
{
    __shared__ float sxt[132][32];
    __shared__ int sch[32];
    int blk = blockIdx.x;
    int b = blk / (TDIM / 32);
    int tBase = (blk % (TDIM / 32)) * 32;
    int tid = threadIdx.x;
    const int* cb = chars + b * TDIM;

    if (tid < 32) sch[tid] = cb[tBase + tid];
    __syncthreads();

    for (int idx = tid; idx < 32 * 64; idx += 256) {
        int tok = idx >> 6, c = idx & 63;
        sxt[c][tok] = emb_byte[sch[tok] * 64 + c];
    }
    for (int idx = tid; idx < 32 * 64; idx += 256) {
        int tok = idx >> 6, c = idx & 63;
        int t = tBase + tok;
        float acc = conv_b[c];
#pragma unroll
        for (int k = 0; k < 4; k++) {
            int tt = t - 3 + k;
            float v = (tt >= 0) ? g_hf[(size_t)(b * TDIM + tt) * 64 + c] : 0.f;
            acc = fmaf(conv_w[c * 4 + k], v, acc);
        }
        sxt[64 + c][tok] = silu_f(acc);
    }
    for (int idx = tid; idx < 128; idx += 256) {
        int tok = idx >> 2, mm = idx & 3;
        int k = 1 << mm;
        int t = tBase + tok;
        float v = 0.f;
        if (t >= k) v = (cb[t] == cb[t - k]) ? 1.f : 0.f;
        sxt[128 + mm][tok] = v;
    }
    __syncthreads();

    u64 acc[16][2];
#pragma unroll
    for (int i = 0; i < 16; i++) { acc[i][0] = 0ull; acc[i][1] = 0ull; }

#pragma unroll 1
    for (int k4 = 0; k4 < 132; k4 += 4) {
        u64 wp[4][2];
#pragma unroll
        for (int j = 0; j < 4; j++) {
            wp[j][0] = pack2(Win[(size_t)(k4 + j) * 512 + tid]);
            wp[j][1] = pack2(Win[(size_t)(k4 + j) * 512 + tid + 256]);
        }
#pragma unroll
        for (int j = 0; j < 4; j++) {
            const ulonglong2* xr = (const ulonglong2*)&sxt[k4 + j][0];
#pragma unroll
            for (int q = 0; q < 8; q++) {
                ulonglong2 x2 = xr[q];
                ffma2(acc[2 * q][0],     x2.x, wp[j][0]);
                ffma2(acc[2 * q][1],     x2.x, wp[j][1]);
                ffma2(acc[2 * q + 1][0], x2.y, wp[j][0]);
                ffma2(acc[2 * q + 1][1], x2.y, wp[j][1]);
            }
        }
    }
#pragma unroll
    for (int cc = 0; cc < 2; cc++) {
        int col = tid + cc * 256;
        float bv = b_in[col];
#pragma unroll
        for (int p = 0; p < 16; p++) {
            size_t r0 = (size_t)(b * TDIM + tBase + 2 * p) * 512 + col;
            g_h[r0]       = silu_f(lo32(acc[p][cc]) + bv);
            g_h[r0 + 512] = silu_f(hi32(acc[p][cc]) + bv);
        }
    }
}

// ---------------------------------------------------------------------------
// K3: gates/drive (verified)
// ---------------------------------------------------------------------------
__global__ void __launch_bounds__(256) k_gates(
    const float* __restrict__ Wg, const float* __restrict__ bg,
    const float* __restrict__ Wi, const float* __restrict__ bi)
{
    __shared__ u64 smbuf[4096];
    float (*sxt)[32] = reinterpret_cast<float(*)[32]>(smbuf);

    int tid = threadIdx.x;
    int col = tid & 63;
    int ks  = tid >> 6;
    int n0 = blockIdx.x * 32;
    int b = n0 / TDIM, t0 = n0 % TDIM;

    u64 acc[16];
#pragma unroll
    for (int i = 0; i < 16; i++) acc[i] = 0ull;

    const float* Wsel = (col < 32) ? Wg : Wi;
    int wcol = col & 31;

    for (int kb = 0; kb < 512; kb += 128) {
        __syncthreads();
        for (int i = tid; i < 32 * 32; i += 256) {
            int tok = i & 31;
            int k4 = (i >> 5) << 2;
            float4 v = *(const float4*)&g_h[(size_t)(n0 + tok) * 512 + kb + k4];
            sxt[k4][tok] = v.x; sxt[k4 + 1][tok] = v.y;
            sxt[k4 + 2][tok] = v.z; sxt[k4 + 3][tok] = v.w;
        }
        __syncthreads();
        int kBase = ks * 32;
#pragma unroll 1
        for (int k = 0; k < 32; k++) {
            u64 wv = pack2(Wsel[(size_t)(kb + kBase + k) * 32 + wcol]);
            const ulonglong2* xr = (const ulonglong2*)&sxt[kBase + k][0];
#pragma unroll
            for (int q = 0; q < 8; q++) {
                ulonglong2 x2 = xr[q];
                ffma2(acc[2 * q],     x2.x, wv);
                ffma2(acc[2 * q + 1], x2.y, wv);
            }
        }
    }
    __syncthreads();
#pragma unroll
    for (int p = 0; p < 16; p++) smbuf[((size_t)ks * 64 + col) * 16 + p] = acc[p];
    __syncthreads();
    if (ks == 0 && col < 32) {
        int j = col;
        float bgv = bg[j], biv = bi[j];
        float* gout = g_gates + (size_t)(b * SSDIM + j) * TDIM + t0;
        float* dout = g_drive + (size_t)(b * SSDIM + j) * TDIM + t0;
#pragma unroll
        for (int p = 0; p < 16; p++) {
            float ag0 = bgv, ag1 = bgv, ai0 = biv, ai1 = biv;
#pragma unroll
            for (int s = 0; s < 4; s++) {
                u64 vg = smbuf[((size_t)s * 64 + j) * 16 + p];
                u64 vi = smbuf[((size_t)s * 64 + 32 + j) * 16 + p];
                ag0 += lo32(vg); ag1 += hi32(vg);
                ai0 += lo32(vi); ai1 += hi32(vi);
            }
            float g0 = 1.f / (1.f + __expf(-ag0));
            float g1 = 1.f / (1.f + __expf(-ag1));
            gout[2 * p]     = g0;
            gout[2 * p + 1] = g1;
            dout[2 * p]     = (1.f - g0) * ai0;
            dout[2 * p + 1] = (1.f - g1) * ai1;
        }
    }
}

// ---------------------------------------------------------------------------
// K4: chunk-parallel TinyScan (verified)
// ---------------------------------------------------------------------------
__global__ void __launch_bounds__(256) k_scan()
{
    int bs = blockIdx.x;
    int j = threadIdx.x;
    const float* ga = g_gates + (size_t)bs * TDIM + j * 32;
    const float* dr = g_drive + (size_t)bs * TDIM + j * 32;
    float a[32], bb[32];
#pragma unroll
    for (int i = 0; i < 32; i++) {
        a[i]  = fmaxf(ga[i], 1e-6f);
        bb[i] = dr[i];
    }
    float cumA = 1.f, cumWB = 0.f;
#pragma unroll
    for (int i = 0; i < 32; i++) {
        cumA *= a[i];
        float inv = 1.f / fmaxf(cumA, 1e-8f);
        cumWB = fmaf(bb[i], inv, cumWB);
    }
    __shared__ float sA[256], sB[256];
    sA[j] = cumA;
    sB[j] = cumA * cumWB;
    __syncthreads();
    for (int d = 1; d < 256; d <<= 1) {
        float a2 = sA[j], b2 = sB[j], a1 = 0.f, b1 = 0.f;
        if (j >= d) { a1 = sA[j - d]; b1 = sB[j - d]; }
        __syncthreads();
        if (j >= d) { sA[j] = a2 * a1; sB[j] = fmaf(a2, b1, b2); }
        __syncthreads();
    }
    float hc = (j == 0) ? 0.f : sB[j - 1];
    cumA = 1.f; cumWB = 0.f;
    float* st = g_states + (size_t)bs * TDIM + j * 32;
#pragma unroll
    for (int i = 0; i < 32; i++) {
        cumA *= a[i];
        float inv = 1.f / fmaxf(cumA, 1e-8f);
        cumWB = fmaf(bb[i], inv, cumWB);
        st[i] = cumA * (hc + cumWB);
    }
}

// ---------------------------------------------------------------------------
// K5a: y = h + states@Wo + bo (verified)
// ---------------------------------------------------------------------------
__global__ void __launch_bounds__(256) k_wo(
    const float* __restrict__ Wo, const float* __restrict__ bo)
{
    __shared__ float sxt[32][32];
    int tid = threadIdx.x;
    int n0 = blockIdx.x * 32;
    int b = n0 / TDIM, t0 = n0 % TDIM;

    for (int i = tid; i < 32 * 8; i += 256) {
        int s = i >> 3, t4 = (i & 7) * 4;
        float4 v = *(const float4*)&g_states[(size_t)(b * SSDIM + s) * TDIM + t0 + t4];
        *(float4*)&sxt[s][t4] = v;
    }
    __syncthreads();

    u64 acc[16][2];
#pragma unroll
    for (int i = 0; i < 16; i++) { acc[i][0] = 0ull; acc[i][1] = 0ull; }

#pragma unroll 1
    for (int k4 = 0; k4 < 32; k4 += 4) {
        u64 wp[4][2];
#pragma unroll
        for (int j = 0; j < 4; j++) {
            wp[j][0] = pack2(Wo[(size_t)(k4 + j) * 512 + tid]);
            wp[j][1] = pack2(Wo[(size_t)(k4 + j) * 512 + tid + 256]);
        }
#pragma unroll
        for (int j = 0; j < 4; j++) {
            const ulonglong2* xr = (const ulonglong2*)&sxt[k4 + j][0];
#pragma unroll
            for (int q = 0; q < 8; q++) {
                ulonglong2 x2 = xr[q];
                ffma2(acc[2 * q][0],     x2.x, wp[j][0]);
                ffma2(acc[2 * q][1],     x2.x, wp[j][1]);
                ffma2(acc[2 * q + 1][0], x2.y, wp[j][0]);
                ffma2(acc[2 * q + 1][1], x2.y, wp[j][1]);
            }
        }
    }
#pragma unroll
    for (int cc = 0; cc < 2; cc++) {
        int col = tid + cc * 256;
        float bv = bo[col];
#pragma unroll
        for (int p = 0; p < 16; p++) {
            size_t r0 = (size_t)(n0 + 2 * p) * 512 + col;
            g_h2[r0]       = lo32(acc[p][cc]) + bv + g_h[r0];
            g_h2[r0 + 512] = hi32(acc[p][cc]) + bv + g_h[r0 + 512];
        }
    }
}

// ---------------------------------------------------------------------------
// K5b: LayerNorm + bf16 hi/lo split write for the tensor path
// ---------------------------------------------------------------------------
__global__ void __launch_bounds__(128) k_ln(
    const float* __restrict__ lng, const float* __restrict__ lnb)
{
    int n = blockIdx.x;
    int tid = threadIdx.x;
    int c = tid * 4;
    float4 y = *(const float4*)&g_h2[(size_t)n * 512 + c];
    float lsum = y.x + y.y + y.z + y.w;
    float lsq  = y.x * y.x + y.y * y.y + y.z * y.z + y.w * y.w;
#pragma unroll
    for (int off = 16; off; off >>= 1) {
        lsum += __shfl_xor_sync(0xffffffffu, lsum, off);
        lsq  += __shfl_xor_sync(0xffffffffu, lsq,  off);
    }
    __shared__ float red[4][2];
    int wip = tid >> 5, lane = tid & 31;
    if (lane == 0) { red[wip][0] = lsum; red[wip][1] = lsq; }
    __syncthreads();
    lsum = red[0][0] + red[1][0] + red[2][0] + red[3][0];
    lsq  = red[0][1] + red[1][1] + red[2][1] + red[3][1];
    float mu = lsum * (1.f / 512.f);
    float var = lsq * (1.f / 512.f) - mu * mu;
    float rstd = rsqrtf(var + 1e-5f);
    float4 g4 = *(const float4*)&lng[c];
    float4 b4 = *(const float4*)&lnb[c];
    float4 o;
    o.x = (y.x - mu) * rstd * g4.x + b4.x;
    o.y = (y.y - mu) * rstd * g4.y + b4.y;
    o.z = (y.z - mu) * rstd * g4.z + b4.z;
    o.w = (y.w - mu) * rstd * g4.w + b4.w;
    *(float4*)&g_h2[(size_t)n * 512 + c] = o;
    float vs[4] = {o.x, o.y, o.z, o.w};
    __nv_bfloat16 bh[4], bl[4];
#pragma unroll
    for (int e = 0; e < 4; e++) {
        bh[e] = __float2bfloat16_rn(vs[e]);
        bl[e] = __float2bfloat16_rn(vs[e] - __bfloat162float(bh[e]));
    }
    size_t base = (size_t)n * 512 + c;
    *(__nv_bfloat162*)&g_xh[base]     = *(__nv_bfloat162*)&bh[0];
    *(__nv_bfloat162*)&g_xh[base + 2] = *(__nv_bfloat162*)&bh[2];
    *(__nv_bfloat162*)&g_xl[base]     = *(__nv_bfloat162*)&bl[0];
    *(__nv_bfloat162*)&g_xl[base + 2] = *(__nv_bfloat162*)&bl[2];
}

// ---------------------------------------------------------------------------
// Weight prep: split W[k][N] f32 into transposed bf16 hi/lo [n*512+k]
// ---------------------------------------------------------------------------
__global__ void __launch_bounds__(256) k_prep_w(
    const float* __restrict__ W, int N, int layer)
{
    int idx = blockIdx.x * 256 + threadIdx.x;
    int k = idx & 511;
    int n = idx >> 9;
    if (n >= N) return;
    float w = W[(size_t)k * N + n];
    __nv_bfloat16 h = __float2bfloat16_rn(w);
    __nv_bfloat16 l = __float2bfloat16_rn(w - __bfloat162float(h));
    g_wbh[layer][(size_t)n * 512 + k] = h;
    g_wbl[layer][(size_t)n * 512 + k] = l;
}

// ---------------------------------------------------------------------------
// Split-bf16 mma.sync GEMM: D = Xh@Wh' + Xl@Wh' + Xh@Wl'  (fp32 accum)
// CTA: 128 tokens x 128 cols x K=512. 8 warps, each 64x32 via m16n8k16.
// 3-stage cp.async pipeline, KT=64. Epilogue from registers.
// ---------------------------------------------------------------------------
#define NKT 8
#define STAGE_BYTES 65536
#define SMEM_MM (3 * STAGE_BYTES)

template<int NOUT, int RESACT, int SPLIT, int WF32>
__global__ void __launch_bounds__(256) k_mma(
    const __nv_bfloat16* __restrict__ xh, const __nv_bfloat16* __restrict__ xl,
    const float* __restrict__ xres,
    const __nv_bfloat16* __restrict__ wh, const __nv_bfloat16* __restrict__ wl,
    const float* __restrict__ bias,
    float* __restrict__ yf, __nv_bfloat16* __restrict__ yh, __nv_bfloat16* __restrict__ yl)
{
    extern __shared__ char dsm[];
    uint32_t smem0 = smem_u32(dsm);
    int tid = threadIdx.x;
    int wid = tid >> 5, lane = tid & 31;
    int wm = wid >> 2, wn = wid & 3;          // warp tile: rows wm*64, cols wn*32
    int m0 = blockIdx.x * 128;
    int n0 = blockIdx.y * 128;

    float c[4][4][4];
#pragma unroll
    for (int i = 0; i < 4; i++)
#pragma unroll
        for (int j = 0; j < 4; j++)
#pragma unroll
            for (int e = 0; e < 4; e++) c[i][j][e] = 0.f;

    // stage fill: 4 tiles (Ah, Al, Bh, Bl), each 128 rows x 64 bf16 (128B/row)
    auto fill = [&](int kt) {
        int stage = kt % 3;
        int kb = kt * 64;
        uint32_t sb = smem0 + stage * STAGE_BYTES;
#pragma unroll
        for (int j = 0; j < 16; j++) {
            int cidx = tid + 256 * j;
            int tile = cidx >> 10;
            int idx = cidx & 1023;
            int row = idx >> 3;
            int c16 = idx & 7;
            uint32_t dst = sb + tile * 16384 + row * 128 + ((c16 ^ (row & 7)) << 4);
            const __nv_bfloat16* src;
            if (tile == 0)      src = xh + (size_t)(m0 + row) * 512 + kb + c16 * 8;
            else if (tile == 1) src = xl + (size_t)(m0 + row) * 512 + kb + c16 * 8;
            else if (tile == 2) src = wh + (size_t)(n0 + row) * 512 + kb + c16 * 8;
            else                src = wl + (size_t)(n0 + row) * 512 + kb + c16 * 8;
            cpasync16(dst, (const void*)src);
        }
        CP_COMMIT();
    };

    fill(0);
    fill(1);

    int la = lane & 15, lh = lane >> 4;

    for (int i = 0; i < NKT; i++) {
        uint32_t sb = smem0 + (i % 3) * STAGE_BYTES;
        if (i < NKT - 1) { CP_WAIT1(); } else { CP_WAIT0(); }
        __syncthreads();
        if (i + 2 < NKT) fill(i + 2);

#pragma unroll
        for (int kc = 0; kc < 4; kc++) {
            int c16 = kc * 2 + lh;
            uint32_t ah[4][4], al[4][4], bhf[2][4], blf[2][4];
#pragma unroll
            for (int mt = 0; mt < 4; mt++)
                ldmx4(ah[mt], tile_addr(sb,         wm * 64 + mt * 16 + la, c16));
#pragma unroll
            for (int mt = 0; mt < 4; mt++)
                ldmx4(al[mt], tile_addr(sb + 16384, wm * 64 + mt * 16 + la, c16));
#pragma unroll
            for (int bt = 0; bt < 2; bt++)
                ldmx4(bhf[bt], tile_addr(sb + 32768, wn * 32 + bt * 16 + la, c16));
#pragma unroll
            for (int bt = 0; bt < 2; bt++)
                ldmx4(blf[bt], tile_addr(sb + 49152, wn * 32 + bt * 16 + la, c16));
#pragma unroll
            for (int mt = 0; mt < 4; mt++) {
#pragma unroll
                for (int nt = 0; nt < 4; nt++) {
                    int bt = nt >> 1, hf = nt & 1;
                    mma16816(c[mt][nt], ah[mt], bhf[bt][hf], bhf[bt][2 + hf]);
                    mma16816(c[mt][nt], al[mt], bhf[bt][hf], bhf[bt][2 + hf]);
                    mma16816(c[mt][nt], ah[mt], blf[bt][hf], blf[bt][2 + hf]);
                }
            }
        }
    }

    // ---- epilogue straight from registers ----
    int r0 = lane >> 2;
    int cp = (lane & 3) * 2;
#pragma unroll
    for (int nt = 0; nt < 4; nt++) {
        int col = n0 + wn * 32 + nt * 8 + cp;
        float2 bv = *(const float2*)&bias[col];
#pragma unroll
        for (int mt = 0; mt < 4; mt++) {
#pragma unroll
            for (int half = 0; half < 2; half++) {
                int row = m0 + wm * 64 + mt * 16 + r0 + half * 8;
                float v0 = c[mt][nt][2 * half]     + bv.x;
                float v1 = c[mt][nt][2 * half + 1] + bv.y;
                if (RESACT) {
                    float2 xr = *(const float2*)&xres[(size_t)row * 512 + col];
                    v0 = xr.x + silu_f(v0);
                    v1 = xr.y + silu_f(v1);
                }
                if (WF32) {
                    *(float2*)&yf[(size_t)row * NOUT + col] = make_float2(v0, v1);
                }
                if (SPLIT) {
                    __nv_bfloat16 h0 = __float2bfloat16_rn(v0);
                    __nv_bfloat16 h1 = __float2bfloat16_rn(v1);
                    __nv_bfloat16 l0 = __float2bfloat16_rn(v0 - __bfloat162float(h0));
                    __nv_bfloat16 l1 = __float2bfloat16_rn(v1 - __bfloat162float(h1));
                    size_t base = (size_t)row * 512 + col;
                    __nv_bfloat162 hp; hp.x = h0; hp.y = h1;
                    __nv_bfloat162 lp; lp.x = l0; lp.y = l1;
                    *(__nv_bfloat162*)&yh[base] = hp;
                    *(__nv_bfloat162*)&yl[base] = lp;
                }
            }
        }
    }
}

// ---------------------------------------------------------------------------
extern "C" void kernel_launch(void* const* d_in, const int* in_sizes, int n_in,
                              void* d_out, int out_size)
{
    const int*   chars    = (const int*)d_in[0];
    const float* emb_byte = (const float*)d_in[1];
    const float* htab     = (const float*)d_in[2];
    const float* Wq       = (const float*)d_in[3];
    const float* bq       = (const float*)d_in[4];
    const float* conv_w   = (const float*)d_in[5];
    const float* conv_b   = (const float*)d_in[6];
    const float* Win      = (const float*)d_in[7];
    const float* b_in     = (const float*)d_in[8];
    const float* Wg       = (const float*)d_in[9];
    const float* bg       = (const float*)d_in[10];
    const float* Wi       = (const float*)d_in[11];
    const float* bi       = (const float*)d_in[12];
    const float* Wo       = (const float*)d_in[13];
    const float* bo       = (const float*)d_in[14];
    const float* lng      = (const float*)d_in[15];
    const float* lnb      = (const float*)d_in[16];
    const float* mlp_w    = (const float*)d_in[17];
    const float* mlp_b    = (const float*)d_in[18];
    const float* Wout     = (const float*)d_in[19];
    const float* bout     = (const float*)d_in[20];
    float* out = (float*)d_out;

    void *p;
    cudaGetSymbolAddress(&p, g_h);   float* gh  = (float*)p;
    cudaGetSymbolAddress(&p, g_h2);  float* gh2 = (float*)p;
    cudaGetSymbolAddress(&p, g_xh);  __nv_bfloat16* xh  = (__nv_bfloat16*)p;
    cudaGetSymbolAddress(&p, g_xl);  __nv_bfloat16* xl  = (__nv_bfloat16*)p;
    cudaGetSymbolAddress(&p, g_x2h); __nv_bfloat16* x2h = (__nv_bfloat16*)p;
    cudaGetSymbolAddress(&p, g_x2l); __nv_bfloat16* x2l = (__nv_bfloat16*)p;
    cudaGetSymbolAddress(&p, g_wbh); __nv_bfloat16* wbh = (__nv_bfloat16*)p;
    cudaGetSymbolAddress(&p, g_wbl); __nv_bfloat16* wbl = (__nv_bfloat16*)p;

    static int attr_done = 0;
    if (!attr_done) {
        cudaFuncSetAttribute(k_mma<512,1,1,1>, cudaFuncAttributeMaxDynamicSharedMemorySize, SMEM_MM);
        cudaFuncSetAttribute(k_mma<512,1,1,0>, cudaFuncAttributeMaxDynamicSharedMemorySize, SMEM_MM);
        cudaFuncSetAttribute(k_mma<256,0,0,1>, cudaFuncAttributeMaxDynamicSharedMemorySize, SMEM_MM);
        attr_done = 1;
    }

    // weight prep (bf16 split + transpose)
    k_prep_w<<<512 * 512 / 256, 256>>>(mlp_w,                 512, 0);
    k_prep_w<<<512 * 512 / 256, 256>>>(mlp_w + 512 * 512,     512, 1);
    k_prep_w<<<512 * 512 / 256, 256>>>(mlp_w + 2 * 512 * 512, 512, 2);
    k_prep_w<<<256 * 512 / 256, 256>>>(Wout,                  256, 3);

    k_hashfeat<<<BT / 8, 256>>>(chars, emb_byte, htab, Wq, bq);
    k_feat_win<<<BT / 32, 256>>>(chars, emb_byte, conv_w, conv_b, Win, b_in);
    k_gates<<<BT / 32, 256>>>(Wg, bg, Wi, bi);
    k_scan<<<BDIM * SSDIM, 256>>>();
    k_wo<<<BT / 32, 256>>>(Wo, bo);
    k_ln<<<BT, 128>>>(lng, lnb);

    dim3 g512(BT / 128, 4), g256(BT / 128, 2);
    // L1: in (xh,xl), resid g_h2 -> f32 g_h + split x2
    k_mma<512,1,1,1><<<g512, 256, SMEM_MM>>>(xh, xl, gh2,
        wbh + 0 * 512 * 512, wbl + 0 * 512 * 512, mlp_b, gh, x2h, x2l);
    // L2: in (x2h,x2l), resid g_h -> f32 g_h2 + split x
    k_mma<512,1,1,1><<<g512, 256, SMEM_MM>>>(x2h, x2l, gh,
        wbh + 1 * 512 * 512, wbl + 1 * 512 * 512, mlp_b + 512, gh2, xh, xl);
    // L3: in (xh,xl), resid g_h2 -> split x2 only
    k_mma<512,1,1,0><<<g512, 256, SMEM_MM>>>(xh, xl, gh2,
        wbh + 2 * 512 * 512, wbl + 2 * 512 * 512, mlp_b + 1024, 0, x2h, x2l);
    // Wout: in (x2h,x2l) -> out f32 [65536,256]
    k_mma<256,0,0,1><<<g256, 256, SMEM_MM>>>(x2h, x2l, 0,
        wbh + 3 * 512 * 512, wbl + 3 * 512 * 512, bout, out, 0, 0);
}